// round 9
// baseline (speedup 1.0000x reference)
#include <cuda_runtime.h>
#include <cuda_fp16.h>
#include <cstdint>

#define BB   128
#define TT   256
#define NH   1024
#define NI   1024
#define NT   256               // 8 warps
#define KBW  256               // k elems per chunk
#define ROWB 528               // smem row bytes (512 + 16 pad, LDSM conflict-free)
#define STAGE_BYTES (64*ROWB)
#define AREG (3*STAGE_BYTES)
#define SMEM_DYN (2*AREG)      // 202752 bytes
#define TX_STD   49152u        // (64 A + 32 W) rows * 512 B
#define TX_FUSED 65536u        // (64 A + 64 W) rows * 512 B

// ---------------- device scratch ----------------
__device__ __align__(16) float  g_s [8][BB*NH];     // fp32 states s0..s7 (s6/s8 never stored)
__device__ __align__(16) __half g_sf[6][BB*NH];     // fp16 states (0,1,2,3,5 used)
__device__ __align__(16) float  g_hbuf[BB*NH];
__device__ __align__(16) __half g_hf[BB*NH];
__device__ __align__(16) __half g_xf[BB*TT*NI];
__device__ __align__(16) __half g_W0t[2048*2048];   // [n][k] fp16, transposed
__device__ __align__(16) __half g_Wst[8][2048*1024];// [n][k] fp16 per gene
__device__ unsigned g_arrive, g_epoch;

// ---------------- primitives ----------------
__device__ __forceinline__ void mma16816(float c[4], const uint32_t a[4],
                                         uint32_t b0, uint32_t b1){
  asm volatile(
    "mma.sync.aligned.m16n8k16.row.col.f32.f16.f16.f32 "
    "{%0,%1,%2,%3},{%4,%5,%6,%7},{%8,%9},{%0,%1,%2,%3};\n"
    : "+f"(c[0]), "+f"(c[1]), "+f"(c[2]), "+f"(c[3])
    : "r"(a[0]), "r"(a[1]), "r"(a[2]), "r"(a[3]), "r"(b0), "r"(b1));
}

__device__ __forceinline__ void ldsm4(uint32_t r[4], uint32_t addr){
  asm volatile("ldmatrix.sync.aligned.m8n8.x4.shared.b16 {%0,%1,%2,%3}, [%4];"
    : "=r"(r[0]), "=r"(r[1]), "=r"(r[2]), "=r"(r[3]) : "r"(addr));
}

__device__ __forceinline__ void bulk512(uint32_t dst, const void* src, uint32_t mbar){
  asm volatile(
    "cp.async.bulk.shared::cta.global.mbarrier::complete_tx::bytes [%0], [%1], %2, [%3];"
    :: "r"(dst), "l"(src), "r"(512u), "r"(mbar) : "memory");
}

__device__ __forceinline__ void expect_tx(uint32_t mbar, uint32_t bytes){
  asm volatile("mbarrier.arrive.expect_tx.shared.b64 _, [%0], %1;"
    :: "r"(mbar), "r"(bytes) : "memory");
}

__device__ __forceinline__ void mbar_wait(uint32_t mbar, int phase){
  uint32_t done;
  asm volatile(
    "{\n\t.reg .pred p;\n\t"
    "mbarrier.try_wait.parity.acquire.cta.shared::cta.b64 p, [%1], %2;\n\t"
    "selp.b32 %0, 1, 0, p;\n\t}"
    : "=r"(done) : "r"(mbar), "r"((uint32_t)phase) : "memory");
  if (!done){
    asm volatile(
      "{\n\t.reg .pred P1;\n\t"
      "WAIT_LOOP_%=:\n\t"
      "mbarrier.try_wait.parity.acquire.cta.shared::cta.b64 P1, [%0], %1, 0x989680;\n\t"
      "@P1 bra.uni WAIT_DONE_%=;\n\t"
      "bra.uni WAIT_LOOP_%=;\n\t"
      "WAIT_DONE_%=:\n\t}"
      :: "r"(mbar), "r"((uint32_t)phase) : "memory");
  }
}

__device__ __forceinline__ void gsync(unsigned &target){
  __syncthreads();
  if (threadIdx.x == 0){
    target += gridDim.x;
    unsigned old;
    asm volatile("atom.add.release.gpu.global.u32 %0, [%1], %2;"
                 : "=r"(old) : "l"(&g_arrive), "r"(1u) : "memory");
    if (old + 1 == target){
      asm volatile("st.release.gpu.global.u32 [%0], %1;" :: "l"(&g_epoch), "r"(target) : "memory");
    } else {
      unsigned e; int spins = 0;
      do {
        asm volatile("ld.acquire.gpu.global.u32 %0, [%1];" : "=r"(e) : "l"(&g_epoch) : "memory");
        if (++spins > 32) __nanosleep(64);
      } while ((int)(e - target) < 0);
    }
  }
  __syncthreads();
}

__device__ __forceinline__ float act_fn(int act, float v){
  switch (act){
    case 0:  return 1.f/(1.f + __expf(-v));
    case 1:  return fmaxf(v, 0.f);
    case 2:  return v;
    default: return tanhf(v);
  }
}

__device__ __forceinline__ uint32_t A_off(int st, int row){
  return (uint32_t)(st*STAGE_BYTES + row*ROWB);
}
__device__ __forceinline__ uint32_t W_off(int st, int row){
  return (uint32_t)(AREG + st*STAGE_BYTES + row*ROWB);
}

// W smem row layout (32 rows per gene block, interleaved per warp):
// row r: block=r>>4 (warp wn), q=r&15: q<8 -> c-col j0+block*8+q ; q>=8 -> h-col (+1024)
__device__ __forceinline__ int w_gcol(int r, int j0){
  int block = r >> 4, q = r & 15;
  int col = j0 + block*8 + (q & 7);
  return ((q >> 3) ? NH : 0) + col;
}

// ---------------- full-K GEMM job (fp16, fused gate epilogue) ----------------
// M=64 rows [m0,m0+64), 16 c-cols [j0,j0+16) paired with 16 h-cols [1024+j0,...).
// FUSED: two weight sets (gene5+gene7) on the same tile; epilogue computes s6,s8
// locally and finishes the step (mean + output writes) -> no F phase.
// 8 warps as 4(M)x2(N): warp = 16 rows x (8c+8h per gene).
template<bool FUSED>
__device__ void job(
    const __half* __restrict__ a1, long a1s, const __half* __restrict__ a2,
    const __half* __restrict__ wt, const __half* __restrict__ wt2, int Kw,
    const float* __restrict__ resid,
    float* __restrict__ outS, __half* __restrict__ outH,
    int m0, int j0, int act, int NC,
    uint32_t sbase, uint32_t mb0, int ph[3], int tid,
    float* __restrict__ out, int t)
{
  const int lane = tid & 31, warp = tid >> 5;
  const int wm = warp >> 1, wn = warp & 1;
  const uint32_t TX = FUSED ? TX_FUSED : TX_STD;

  float C[FUSED?4:2][4];
  #pragma unroll
  for (int n=0;n<(FUSED?4:2);n++)
    #pragma unroll
    for (int q=0;q<4;q++) C[n][q]=0.f;

  auto load_chunk = [&](int c, int st){
    int k0 = c*KBW;
    uint32_t mbar = mb0 + st*8;
    if (tid < 64){
      int row = tid;
      const __half* src;
      if (a2 && k0 >= 1024) src = a2 + (size_t)(m0+row)*NH + (k0-1024);
      else                  src = a1 + (size_t)(m0+row)*a1s + k0;
      bulk512(sbase + A_off(st,row), src, mbar);
    } else if (tid < (FUSED ? 128 : 96)){
      int n = tid - 64;
      const __half* w = wt;
      int r = n;
      if (FUSED && n >= 32){ w = wt2; r = n - 32; }
      bulk512(sbase + W_off(st,n), w + (size_t)w_gcol(r,j0)*Kw + k0, mbar);
    }
  };

  if (tid == 0){
    expect_tx(mb0,    TX);
    expect_tx(mb0+8,  TX);
    expect_tx(mb0+16, TX);
  }
  __syncthreads();
  load_chunk(0,0); load_chunk(1,1); load_chunk(2,2);

  const uint32_t a_row  = (uint32_t)(wm*16 + (lane & 15));
  const uint32_t a_koff = (uint32_t)((lane >> 4) * 16);
  const int sub = lane >> 3;
  const uint32_t b_row  = (uint32_t)(wn*16 + ((sub >> 1) << 3) + (lane & 7));
  const uint32_t b_koff = (uint32_t)((sub & 1) * 16);

  for (int c=0; c<NC; c++){
    const int st = c % 3;
    const uint32_t mbar = mb0 + st*8;
    mbar_wait(mbar, ph[st]); ph[st] ^= 1;
    if (c + 3 < NC && tid == 0) expect_tx(mbar, TX);

    const uint32_t aB = sbase + A_off(st, a_row) + a_koff;
    const uint32_t bB = sbase + W_off(st, b_row) + b_koff;

    #pragma unroll
    for (int kk = 0; kk < KBW; kk += 16){
      const uint32_t kb = (uint32_t)(kk*2);
      uint32_t A4[4], B5[4];
      ldsm4(A4, aB + kb);
      ldsm4(B5, bB + kb);
      mma16816(C[0], A4, B5[0], B5[1]);   // c-cols
      mma16816(C[1], A4, B5[2], B5[3]);   // h-cols
      if (FUSED){
        uint32_t B7[4];
        ldsm4(B7, bB + 32*ROWB + kb);
        mma16816(C[2], A4, B7[0], B7[1]);
        mma16816(C[3], A4, B7[2], B7[3]);
      }
    }
    __syncthreads();
    if (c + 3 < NC) load_chunk(c+3, st);
  }

  // epilogue
  const int colb = j0 + wn*8 + 2*(lane&3);
  #pragma unroll
  for (int half=0; half<2; half++){
    const int row = m0 + wm*16 + (lane>>2) + half*8;
    const int q0 = half*2;
    const int idx = row*NH + colb;
    if (!FUSED){
      float sp0 = __ldcg(resid + idx), sp1 = __ldcg(resid + idx + 1);
      float g0 = 1.f/(1.f + __expf(-C[0][q0]));
      float g1 = 1.f/(1.f + __expf(-C[0][q0+1]));
      float v0 = fmaf(g0, act_fn(act, C[1][q0])   - sp0, sp0);
      float v1 = fmaf(g1, act_fn(act, C[1][q0+1]) - sp1, sp1);
      *(float2*)(outS + idx) = make_float2(v0, v1);
      if (outH) *(__half2*)(outH + idx) = __floats2half2_rn(v0, v1);
    } else {
      // gene5 (sigmoid act) -> s6 ; gene7 (relu act) -> s8 ; resid = s5
      float s5v0 = __ldcg(resid + idx), s5v1 = __ldcg(resid + idx + 1);
      float g50 = 1.f/(1.f + __expf(-C[0][q0]));
      float g51 = 1.f/(1.f + __expf(-C[0][q0+1]));
      float s60 = fmaf(g50, 1.f/(1.f + __expf(-C[1][q0]))   - s5v0, s5v0);
      float s61 = fmaf(g51, 1.f/(1.f + __expf(-C[1][q0+1])) - s5v1, s5v1);
      float g70 = 1.f/(1.f + __expf(-C[2][q0]));
      float g71 = 1.f/(1.f + __expf(-C[2][q0+1]));
      float s80 = fmaf(g70, fmaxf(C[3][q0],  0.f) - s5v0, s5v0);
      float s81 = fmaf(g71, fmaxf(C[3][q0+1],0.f) - s5v1, s5v1);
      float2 s1v = *(const float2*)(&g_s[1][idx]);
      float2 s2v = *(const float2*)(&g_s[2][idx]);
      float2 s3v = *(const float2*)(&g_s[3][idx]);
      float2 s4v = *(const float2*)(&g_s[4][idx]);
      float2 s7v = *(const float2*)(&g_s[7][idx]);
      float m0v = (s1v.x+s2v.x+s3v.x+s4v.x+s5v0+s60+s7v.x+s80)*0.125f;
      float m1v = (s1v.y+s2v.y+s3v.y+s4v.y+s5v1+s61+s7v.y+s81)*0.125f;
      *(float2*)(&g_hbuf[idx]) = make_float2(m0v, m1v);
      *(__half2*)(&g_hf[idx]) = __floats2half2_rn(m0v, m1v);
      *(float2*)(&out[((size_t)row*TT + t)*NH + colb]) = make_float2(m0v, m1v);
      if (t == TT-1) *(float2*)(&out[(size_t)BB*TT*NH + idx]) = make_float2(m0v, m1v);
    }
  }
}

// ---------------- persistent scan kernel ----------------
__global__ void __launch_bounds__(NT,1) rnn_persistent(float* __restrict__ out){
  extern __shared__ __align__(16) unsigned char dsm[];
  __shared__ __align__(8) uint64_t s_mbar[3];

  const int tid = threadIdx.x;
  uint32_t sbase, mb0;
  { uint32_t a; asm("{ .reg .u64 t; cvta.to.shared.u64 t, %1; cvt.u32.u64 %0, t; }" : "=r"(a) : "l"(dsm)); sbase = a; }
  { uint32_t a; asm("{ .reg .u64 t; cvta.to.shared.u64 t, %1; cvt.u32.u64 %0, t; }" : "=r"(a) : "l"(&s_mbar[0])); mb0 = a; }

  if (tid == 0){
    #pragma unroll
    for (int b=0;b<3;b++)
      asm volatile("mbarrier.init.shared.b64 [%0], %1;" :: "r"(mb0+b*8), "r"(1u) : "memory");
  }
  __syncthreads();

  int ph[3] = {0,0,0};
  unsigned target = 0;

  for (int t = 0; t < TT; t++){
    // G0: [x_t | h] @ W0 -> s0 (tanh, resid h). 128 jobs, K=2048
    for (int it = blockIdx.x; it < 128; it += gridDim.x){
      int m0 = (it >= 64) ? 64 : 0, j0 = (it & 63)*16;
      job<false>(g_xf + (size_t)t*NI, (long)TT*NI, g_hf,
                 g_W0t, nullptr, 2048, g_hbuf, g_s[0], g_sf[0],
                 m0, j0, 3, 8, sbase, mb0, ph, tid, out, t);
    }
    gsync(target);

    // G1: gene0 (sigmoid) s0 -> s1. 128 jobs, K=1024
    for (int it = blockIdx.x; it < 128; it += gridDim.x){
      int m0 = (it >= 64) ? 64 : 0, j0 = (it & 63)*16;
      job<false>(g_sf[0], NH, nullptr, g_Wst[0], nullptr, 1024,
                 g_s[0], g_s[1], g_sf[1], m0, j0, 0, 4, sbase, mb0, ph, tid, out, t);
    }
    gsync(target);

    // G2: genes 1,2,3 from s1 -> s2(relu), s3(relu), s4(identity). 384 jobs
    for (int it = blockIdx.x; it < 384; it += gridDim.x){
      int gi = 1 + (it >> 7), rem = it & 127;
      int m0 = (rem >= 64) ? 64 : 0, j0 = (rem & 63)*16;
      int dst = gi + 1;
      job<false>(g_sf[1], NH, nullptr, g_Wst[gi], nullptr, 1024,
                 g_s[1], g_s[dst], (dst < 4) ? g_sf[dst] : (__half*)nullptr,
                 m0, j0, (gi==3)?2:1, 4, sbase, mb0, ph, tid, out, t);
    }
    gsync(target);

    // G3: gene4 (tanh) s2->s5 ; gene6 (tanh) s3->s7. 256 jobs
    for (int it = blockIdx.x; it < 256; it += gridDim.x){
      int slot = it >> 7, rem = it & 127;
      int m0 = (rem >= 64) ? 64 : 0, j0 = (rem & 63)*16;
      int gi = 4 + slot*2, src = 2 + slot, dst = gi + 1;  // 5 or 7
      job<false>(g_sf[src], NH, nullptr, g_Wst[gi], nullptr, 1024,
                 g_s[src], g_s[dst], (dst==5) ? g_sf[5] : (__half*)nullptr,
                 m0, j0, 3, 4, sbase, mb0, ph, tid, out, t);
    }
    gsync(target);

    // G4+F fused: gene5+gene7 from s5 -> s6,s8 locally; h=mean(s1..s8); out writes.
    for (int it = blockIdx.x; it < 128; it += gridDim.x){
      int m0 = (it >= 64) ? 64 : 0, j0 = (it & 63)*16;
      job<true>(g_sf[5], NH, nullptr, g_Wst[5], g_Wst[7], 1024,
                g_s[5], nullptr, nullptr, m0, j0, 0, 4, sbase, mb0, ph, tid, out, t);
    }
    gsync(target);
  }
}

// ---------------- prologue helpers ----------------
__global__ void tohalf_kernel(const float* __restrict__ src, __half* __restrict__ dst,
                              float* __restrict__ fcopy, int n){
  int i = blockIdx.x*blockDim.x + threadIdx.x;
  int stride = gridDim.x*blockDim.x;
  for (; i < n; i += stride){
    float v = src[i];
    dst[i] = __float2half_rn(v);
    if (fcopy) fcopy[i] = v;
  }
}

__global__ void thalf_kernel(const float* __restrict__ in, __half* __restrict__ outh,
                             int K, int N){
  __shared__ float tile[32][33];
  const float* src = in + (size_t)blockIdx.z*K*N;
  __half* oh = outh + (size_t)blockIdx.z*N*K;
  int tx = threadIdx.x, ty = threadIdx.y;
  int n0 = blockIdx.x*32, k0 = blockIdx.y*32;
  #pragma unroll
  for (int r=0;r<4;r++)
    tile[ty + r*8][tx] = src[(size_t)(k0 + ty + r*8)*N + n0 + tx];
  __syncthreads();
  #pragma unroll
  for (int r=0;r<4;r++)
    oh[(size_t)(n0 + ty + r*8)*K + k0 + tx] = __float2half_rn(tile[tx][ty + r*8]);
}

__global__ void reset_kernel(){ g_arrive = 0; g_epoch = 0; }

// ---------------- host launch ----------------
extern "C" void kernel_launch(void* const* d_in, const int* in_sizes, int n_in,
                              void* d_out, int out_size){
  const float *x=nullptr, *h0=nullptr, *W0=nullptr, *Ws=nullptr;
  for (int i=0;i<n_in;i++){
    long n = in_sizes[i];
    if      (n == (long)BB*TT*NI)   x  = (const float*)d_in[i];
    else if (n == (long)BB*NH)      h0 = (const float*)d_in[i];
    else if (n == (long)2048*2048)  W0 = (const float*)d_in[i];
    else if (n == (long)8*NH*2048)  Ws = (const float*)d_in[i];
  }
  if (!x || !h0 || !W0 || !Ws) return;
  float* out = (float*)d_out;

  void* p;
  cudaGetSymbolAddress(&p, g_hbuf); float*  h_p  = (float*)p;
  cudaGetSymbolAddress(&p, g_hf);   __half* hf_p = (__half*)p;
  cudaGetSymbolAddress(&p, g_xf);   __half* xf_p = (__half*)p;
  cudaGetSymbolAddress(&p, g_W0t);  __half* w0_p = (__half*)p;
  cudaGetSymbolAddress(&p, g_Wst);  __half* ws_p = (__half*)p;

  cudaFuncSetAttribute(rnn_persistent, cudaFuncAttributeMaxDynamicSharedMemorySize, SMEM_DYN);

  int dev = 0, nsm = 0;
  cudaGetDevice(&dev);
  cudaDeviceGetAttribute(&nsm, cudaDevAttrMultiProcessorCount, dev);

  thalf_kernel<<<dim3(64,64,1), dim3(32,8)>>>(W0, w0_p, 2048, 2048);
  thalf_kernel<<<dim3(64,32,8), dim3(32,8)>>>(Ws, ws_p, 1024, 2048);
  tohalf_kernel<<<8192,256>>>(x, xf_p, nullptr, BB*TT*NI);
  tohalf_kernel<<<512,256>>>(h0, hf_p, h_p, BB*NH);
  reset_kernel<<<1,1>>>();

  rnn_persistent<<<nsm, NT, SMEM_DYN>>>(out);
  (void)out_size;
}

// round 10
// speedup vs baseline: 1.0017x; 1.0017x over previous
#include <cuda_runtime.h>
#include <cuda_fp16.h>
#include <cstdint>

#define BB   128
#define TT   256
#define NH   1024
#define NI   1024
#define NT   256               // 8 warps
#define KBW  256               // k elems per chunk
#define ROWB 528               // smem row bytes (512 + 16 pad, LDSM conflict-free)
#define STAGE_BYTES (64*ROWB)
#define AREG (3*STAGE_BYTES)
#define SMEM_DYN (2*AREG)      // 202752 bytes
#define TX_STD   49152u        // (64 A + 32 W) rows * 512 B
#define TX_FUSED 65536u        // (64 A + 64 W) rows * 512 B

// ---------------- device scratch ----------------
__device__ __align__(16) float  g_s [8][BB*NH];     // fp32 states s0..s7 (s6/s8 never stored)
__device__ __align__(16) __half g_sf[6][BB*NH];     // fp16 states (0,1,2,3,5 used)
__device__ __align__(16) float  g_hbuf[BB*NH];
__device__ __align__(16) __half g_hf[BB*NH];
__device__ __align__(16) __half g_xf[BB*TT*NI];
__device__ __align__(16) __half g_W0t[2048*2048];   // [n][k] fp16, transposed
__device__ __align__(16) __half g_Wst[8][2048*1024];// [n][k] fp16 per gene
__device__ unsigned g_arrive, g_epoch;

// ---------------- primitives ----------------
__device__ __forceinline__ void mma16816(float c[4], const uint32_t a[4],
                                         uint32_t b0, uint32_t b1){
  asm volatile(
    "mma.sync.aligned.m16n8k16.row.col.f32.f16.f16.f32 "
    "{%0,%1,%2,%3},{%4,%5,%6,%7},{%8,%9},{%0,%1,%2,%3};\n"
    : "+f"(c[0]), "+f"(c[1]), "+f"(c[2]), "+f"(c[3])
    : "r"(a[0]), "r"(a[1]), "r"(a[2]), "r"(a[3]), "r"(b0), "r"(b1));
}

__device__ __forceinline__ void ldsm4(uint32_t r[4], uint32_t addr){
  asm volatile("ldmatrix.sync.aligned.m8n8.x4.shared.b16 {%0,%1,%2,%3}, [%4];"
    : "=r"(r[0]), "=r"(r[1]), "=r"(r[2]), "=r"(r[3]) : "r"(addr));
}

__device__ __forceinline__ void bulk512(uint32_t dst, const void* src, uint32_t mbar){
  asm volatile(
    "cp.async.bulk.shared::cta.global.mbarrier::complete_tx::bytes [%0], [%1], %2, [%3];"
    :: "r"(dst), "l"(src), "r"(512u), "r"(mbar) : "memory");
}

__device__ __forceinline__ void expect_tx(uint32_t mbar, uint32_t bytes){
  asm volatile("mbarrier.arrive.expect_tx.shared.b64 _, [%0], %1;"
    :: "r"(mbar), "r"(bytes) : "memory");
}

__device__ __forceinline__ void mbar_wait(uint32_t mbar, int phase){
  uint32_t done;
  asm volatile(
    "{\n\t.reg .pred p;\n\t"
    "mbarrier.try_wait.parity.acquire.cta.shared::cta.b64 p, [%1], %2;\n\t"
    "selp.b32 %0, 1, 0, p;\n\t}"
    : "=r"(done) : "r"(mbar), "r"((uint32_t)phase) : "memory");
  if (!done){
    asm volatile(
      "{\n\t.reg .pred P1;\n\t"
      "WAIT_LOOP_%=:\n\t"
      "mbarrier.try_wait.parity.acquire.cta.shared::cta.b64 P1, [%0], %1, 0x989680;\n\t"
      "@P1 bra.uni WAIT_DONE_%=;\n\t"
      "bra.uni WAIT_LOOP_%=;\n\t"
      "WAIT_DONE_%=:\n\t}"
      :: "r"(mbar), "r"((uint32_t)phase) : "memory");
  }
}

__device__ __forceinline__ void gsync(unsigned &target){
  __syncthreads();
  if (threadIdx.x == 0){
    target += gridDim.x;
    unsigned old;
    asm volatile("atom.add.release.gpu.global.u32 %0, [%1], %2;"
                 : "=r"(old) : "l"(&g_arrive), "r"(1u) : "memory");
    if (old + 1 == target){
      asm volatile("st.release.gpu.global.u32 [%0], %1;" :: "l"(&g_epoch), "r"(target) : "memory");
    } else {
      unsigned e; int spins = 0;
      do {
        asm volatile("ld.acquire.gpu.global.u32 %0, [%1];" : "=r"(e) : "l"(&g_epoch) : "memory");
        if (++spins > 32) __nanosleep(64);
      } while ((int)(e - target) < 0);
    }
  }
  __syncthreads();
}

__device__ __forceinline__ float act_fn(int act, float v){
  switch (act){
    case 0:  return 1.f/(1.f + __expf(-v));
    case 1:  return fmaxf(v, 0.f);
    case 2:  return v;
    default: return tanhf(v);
  }
}

__device__ __forceinline__ uint32_t A_off(int st, int row){
  return (uint32_t)(st*STAGE_BYTES + row*ROWB);
}
__device__ __forceinline__ uint32_t W_off(int st, int row){
  return (uint32_t)(AREG + st*STAGE_BYTES + row*ROWB);
}

// W smem row layout (32 rows per gene block, interleaved per warp):
// row r: block=r>>4 (warp wn), q=r&15: q<8 -> c-col j0+block*8+q ; q>=8 -> h-col (+1024)
__device__ __forceinline__ int w_gcol(int r, int j0){
  int block = r >> 4, q = r & 15;
  int col = j0 + block*8 + (q & 7);
  return ((q >> 3) ? NH : 0) + col;
}

// ---------------- full-K GEMM job (fp16, fused gate epilogue) ----------------
// M=64 rows [m0,m0+64), 16 c-cols [j0,j0+16) paired with 16 h-cols [1024+j0,...).
// FUSED: two weight sets (gene5+gene7) on the same tile; epilogue computes s6,s8
// locally and finishes the step (mean + output writes) -> no F phase.
// 8 warps as 4(M)x2(N): warp = 16 rows x (8c+8h per gene).
template<bool FUSED>
__device__ void job(
    const __half* __restrict__ a1, long a1s, const __half* __restrict__ a2,
    const __half* __restrict__ wt, const __half* __restrict__ wt2, int Kw,
    const float* __restrict__ resid,
    float* __restrict__ outS, __half* __restrict__ outH,
    int m0, int j0, int act, int NC,
    uint32_t sbase, uint32_t mb0, int ph[3], int tid,
    float* __restrict__ out, int t)
{
  const int lane = tid & 31, warp = tid >> 5;
  const int wm = warp >> 1, wn = warp & 1;
  const uint32_t TX = FUSED ? TX_FUSED : TX_STD;

  float C[FUSED?4:2][4];
  #pragma unroll
  for (int n=0;n<(FUSED?4:2);n++)
    #pragma unroll
    for (int q=0;q<4;q++) C[n][q]=0.f;

  auto load_chunk = [&](int c, int st){
    int k0 = c*KBW;
    uint32_t mbar = mb0 + st*8;
    if (tid < 64){
      int row = tid;
      const __half* src;
      if (a2 && k0 >= 1024) src = a2 + (size_t)(m0+row)*NH + (k0-1024);
      else                  src = a1 + (size_t)(m0+row)*a1s + k0;
      bulk512(sbase + A_off(st,row), src, mbar);
    } else if (tid < (FUSED ? 128 : 96)){
      int n = tid - 64;
      const __half* w = wt;
      int r = n;
      if (FUSED && n >= 32){ w = wt2; r = n - 32; }
      bulk512(sbase + W_off(st,n), w + (size_t)w_gcol(r,j0)*Kw + k0, mbar);
    }
  };

  if (tid == 0){
    expect_tx(mb0,    TX);
    expect_tx(mb0+8,  TX);
    expect_tx(mb0+16, TX);
  }
  __syncthreads();
  load_chunk(0,0); load_chunk(1,1); load_chunk(2,2);

  const uint32_t a_row  = (uint32_t)(wm*16 + (lane & 15));
  const uint32_t a_koff = (uint32_t)((lane >> 4) * 16);
  const int sub = lane >> 3;
  const uint32_t b_row  = (uint32_t)(wn*16 + ((sub >> 1) << 3) + (lane & 7));
  const uint32_t b_koff = (uint32_t)((sub & 1) * 16);

  for (int c=0; c<NC; c++){
    const int st = c % 3;
    const uint32_t mbar = mb0 + st*8;
    mbar_wait(mbar, ph[st]); ph[st] ^= 1;
    if (c + 3 < NC && tid == 0) expect_tx(mbar, TX);

    const uint32_t aB = sbase + A_off(st, a_row) + a_koff;
    const uint32_t bB = sbase + W_off(st, b_row) + b_koff;

    #pragma unroll
    for (int kk = 0; kk < KBW; kk += 16){
      const uint32_t kb = (uint32_t)(kk*2);
      uint32_t A4[4], B5[4];
      ldsm4(A4, aB + kb);
      ldsm4(B5, bB + kb);
      mma16816(C[0], A4, B5[0], B5[1]);   // c-cols
      mma16816(C[1], A4, B5[2], B5[3]);   // h-cols
      if (FUSED){
        uint32_t B7[4];
        ldsm4(B7, bB + 32*ROWB + kb);
        mma16816(C[2], A4, B7[0], B7[1]);
        mma16816(C[3], A4, B7[2], B7[3]);
      }
    }
    __syncthreads();
    if (c + 3 < NC) load_chunk(c+3, st);
  }

  // epilogue
  const int colb = j0 + wn*8 + 2*(lane&3);
  #pragma unroll
  for (int half=0; half<2; half++){
    const int row = m0 + wm*16 + (lane>>2) + half*8;
    const int q0 = half*2;
    const int idx = row*NH + colb;
    if (!FUSED){
      float sp0 = __ldcg(resid + idx), sp1 = __ldcg(resid + idx + 1);
      float g0 = 1.f/(1.f + __expf(-C[0][q0]));
      float g1 = 1.f/(1.f + __expf(-C[0][q0+1]));
      float v0 = fmaf(g0, act_fn(act, C[1][q0])   - sp0, sp0);
      float v1 = fmaf(g1, act_fn(act, C[1][q0+1]) - sp1, sp1);
      *(float2*)(outS + idx) = make_float2(v0, v1);
      if (outH) *(__half2*)(outH + idx) = __floats2half2_rn(v0, v1);
    } else {
      // gene5 (sigmoid act) -> s6 ; gene7 (relu act) -> s8 ; resid = s5
      float s5v0 = __ldcg(resid + idx), s5v1 = __ldcg(resid + idx + 1);
      float g50 = 1.f/(1.f + __expf(-C[0][q0]));
      float g51 = 1.f/(1.f + __expf(-C[0][q0+1]));
      float s60 = fmaf(g50, 1.f/(1.f + __expf(-C[1][q0]))   - s5v0, s5v0);
      float s61 = fmaf(g51, 1.f/(1.f + __expf(-C[1][q0+1])) - s5v1, s5v1);
      float g70 = 1.f/(1.f + __expf(-C[2][q0]));
      float g71 = 1.f/(1.f + __expf(-C[2][q0+1]));
      float s80 = fmaf(g70, fmaxf(C[3][q0],  0.f) - s5v0, s5v0);
      float s81 = fmaf(g71, fmaxf(C[3][q0+1],0.f) - s5v1, s5v1);
      float2 s1v = *(const float2*)(&g_s[1][idx]);
      float2 s2v = *(const float2*)(&g_s[2][idx]);
      float2 s3v = *(const float2*)(&g_s[3][idx]);
      float2 s4v = *(const float2*)(&g_s[4][idx]);
      float2 s7v = *(const float2*)(&g_s[7][idx]);
      float m0v = (s1v.x+s2v.x+s3v.x+s4v.x+s5v0+s60+s7v.x+s80)*0.125f;
      float m1v = (s1v.y+s2v.y+s3v.y+s4v.y+s5v1+s61+s7v.y+s81)*0.125f;
      *(float2*)(&g_hbuf[idx]) = make_float2(m0v, m1v);
      *(__half2*)(&g_hf[idx]) = __floats2half2_rn(m0v, m1v);
      *(float2*)(&out[((size_t)row*TT + t)*NH + colb]) = make_float2(m0v, m1v);
      if (t == TT-1) *(float2*)(&out[(size_t)BB*TT*NH + idx]) = make_float2(m0v, m1v);
    }
  }
}

// ---------------- persistent scan kernel ----------------
__global__ void __launch_bounds__(NT,1) rnn_persistent(float* __restrict__ out){
  extern __shared__ __align__(16) unsigned char dsm[];
  __shared__ __align__(8) uint64_t s_mbar[3];

  const int tid = threadIdx.x;
  uint32_t sbase, mb0;
  { uint32_t a; asm("{ .reg .u64 t; cvta.to.shared.u64 t, %1; cvt.u32.u64 %0, t; }" : "=r"(a) : "l"(dsm)); sbase = a; }
  { uint32_t a; asm("{ .reg .u64 t; cvta.to.shared.u64 t, %1; cvt.u32.u64 %0, t; }" : "=r"(a) : "l"(&s_mbar[0])); mb0 = a; }

  if (tid == 0){
    #pragma unroll
    for (int b=0;b<3;b++)
      asm volatile("mbarrier.init.shared.b64 [%0], %1;" :: "r"(mb0+b*8), "r"(1u) : "memory");
  }
  __syncthreads();

  int ph[3] = {0,0,0};
  unsigned target = 0;

  for (int t = 0; t < TT; t++){
    // G0: [x_t | h] @ W0 -> s0 (tanh, resid h). 128 jobs, K=2048
    for (int it = blockIdx.x; it < 128; it += gridDim.x){
      int m0 = (it >= 64) ? 64 : 0, j0 = (it & 63)*16;
      job<false>(g_xf + (size_t)t*NI, (long)TT*NI, g_hf,
                 g_W0t, nullptr, 2048, g_hbuf, g_s[0], g_sf[0],
                 m0, j0, 3, 8, sbase, mb0, ph, tid, out, t);
    }
    gsync(target);

    // G1: gene0 (sigmoid) s0 -> s1. 128 jobs, K=1024
    for (int it = blockIdx.x; it < 128; it += gridDim.x){
      int m0 = (it >= 64) ? 64 : 0, j0 = (it & 63)*16;
      job<false>(g_sf[0], NH, nullptr, g_Wst[0], nullptr, 1024,
                 g_s[0], g_s[1], g_sf[1], m0, j0, 0, 4, sbase, mb0, ph, tid, out, t);
    }
    gsync(target);

    // G2: genes 1,2,3 from s1 -> s2(relu), s3(relu), s4(identity). 384 jobs
    for (int it = blockIdx.x; it < 384; it += gridDim.x){
      int gi = 1 + (it >> 7), rem = it & 127;
      int m0 = (rem >= 64) ? 64 : 0, j0 = (rem & 63)*16;
      int dst = gi + 1;
      job<false>(g_sf[1], NH, nullptr, g_Wst[gi], nullptr, 1024,
                 g_s[1], g_s[dst], (dst < 4) ? g_sf[dst] : (__half*)nullptr,
                 m0, j0, (gi==3)?2:1, 4, sbase, mb0, ph, tid, out, t);
    }
    gsync(target);

    // G3: gene4 (tanh) s2->s5 ; gene6 (tanh) s3->s7. 256 jobs
    for (int it = blockIdx.x; it < 256; it += gridDim.x){
      int slot = it >> 7, rem = it & 127;
      int m0 = (rem >= 64) ? 64 : 0, j0 = (rem & 63)*16;
      int gi = 4 + slot*2, src = 2 + slot, dst = gi + 1;  // 5 or 7
      job<false>(g_sf[src], NH, nullptr, g_Wst[gi], nullptr, 1024,
                 g_s[src], g_s[dst], (dst==5) ? g_sf[5] : (__half*)nullptr,
                 m0, j0, 3, 4, sbase, mb0, ph, tid, out, t);
    }
    gsync(target);

    // G4+F fused: gene5+gene7 from s5 -> s6,s8 locally; h=mean(s1..s8); out writes.
    for (int it = blockIdx.x; it < 128; it += gridDim.x){
      int m0 = (it >= 64) ? 64 : 0, j0 = (it & 63)*16;
      job<true>(g_sf[5], NH, nullptr, g_Wst[5], g_Wst[7], 1024,
                g_s[5], nullptr, nullptr, m0, j0, 0, 4, sbase, mb0, ph, tid, out, t);
    }
    gsync(target);
  }
}

// ---------------- prologue helpers ----------------
__global__ void tohalf_kernel(const float* __restrict__ src, __half* __restrict__ dst,
                              float* __restrict__ fcopy, int n){
  int i = blockIdx.x*blockDim.x + threadIdx.x;
  int stride = gridDim.x*blockDim.x;
  for (; i < n; i += stride){
    float v = src[i];
    dst[i] = __float2half_rn(v);
    if (fcopy) fcopy[i] = v;
  }
}

__global__ void thalf_kernel(const float* __restrict__ in, __half* __restrict__ outh,
                             int K, int N){
  __shared__ float tile[32][33];
  const float* src = in + (size_t)blockIdx.z*K*N;
  __half* oh = outh + (size_t)blockIdx.z*N*K;
  int tx = threadIdx.x, ty = threadIdx.y;
  int n0 = blockIdx.x*32, k0 = blockIdx.y*32;
  #pragma unroll
  for (int r=0;r<4;r++)
    tile[ty + r*8][tx] = src[(size_t)(k0 + ty + r*8)*N + n0 + tx];
  __syncthreads();
  #pragma unroll
  for (int r=0;r<4;r++)
    oh[(size_t)(n0 + ty + r*8)*K + k0 + tx] = __float2half_rn(tile[tx][ty + r*8]);
}

__global__ void reset_kernel(){ g_arrive = 0; g_epoch = 0; }

// ---------------- host launch ----------------
extern "C" void kernel_launch(void* const* d_in, const int* in_sizes, int n_in,
                              void* d_out, int out_size){
  const float *x=nullptr, *h0=nullptr, *W0=nullptr, *Ws=nullptr;
  for (int i=0;i<n_in;i++){
    long n = in_sizes[i];
    if      (n == (long)BB*TT*NI)   x  = (const float*)d_in[i];
    else if (n == (long)BB*NH)      h0 = (const float*)d_in[i];
    else if (n == (long)2048*2048)  W0 = (const float*)d_in[i];
    else if (n == (long)8*NH*2048)  Ws = (const float*)d_in[i];
  }
  if (!x || !h0 || !W0 || !Ws) return;
  float* out = (float*)d_out;

  void* p;
  cudaGetSymbolAddress(&p, g_hbuf); float*  h_p  = (float*)p;
  cudaGetSymbolAddress(&p, g_hf);   __half* hf_p = (__half*)p;
  cudaGetSymbolAddress(&p, g_xf);   __half* xf_p = (__half*)p;
  cudaGetSymbolAddress(&p, g_W0t);  __half* w0_p = (__half*)p;
  cudaGetSymbolAddress(&p, g_Wst);  __half* ws_p = (__half*)p;

  cudaFuncSetAttribute(rnn_persistent, cudaFuncAttributeMaxDynamicSharedMemorySize, SMEM_DYN);

  int dev = 0, nsm = 0;
  cudaGetDevice(&dev);
  cudaDeviceGetAttribute(&nsm, cudaDevAttrMultiProcessorCount, dev);

  thalf_kernel<<<dim3(64,64,1), dim3(32,8)>>>(W0, w0_p, 2048, 2048);
  thalf_kernel<<<dim3(64,32,8), dim3(32,8)>>>(Ws, ws_p, 1024, 2048);
  tohalf_kernel<<<8192,256>>>(x, xf_p, nullptr, BB*TT*NI);
  tohalf_kernel<<<512,256>>>(h0, hf_p, h_p, BB*NH);
  reset_kernel<<<1,1>>>();

  rnn_persistent<<<nsm, NT, SMEM_DYN>>>(out);
  (void)out_size;
}

// round 12
// speedup vs baseline: 1.3144x; 1.3121x over previous
#include <cuda_runtime.h>
#include <cuda_fp16.h>
#include <cstdint>

#define BB   128
#define TT   256
#define NH   1024
#define NI   1024
#define NT   256
#define STAGE 65536u
#define SMEM_DYN (3*65536)

// ---------------- device scratch (swizzled tile layouts) ----------------
// states (0..5) + h(6): [state][m-half][k-subtile][64 rows x 128B, SW128 swizzled]
__device__ __align__(128) unsigned char g_sw[7][2][16][8192];
// x: [t][m-half][k-subtile][8192]
__device__ __align__(128) unsigned char g_xw[TT][2][16][8192];
// W0: [j0-tile 64][32 k-subtiles x 4096B]  (rows interleaved c/h per pair)
__device__ __align__(128) unsigned char g_w0w[64][32*4096];
// genes: [gene][j0-tile][16 k-subtiles x 4096B]
__device__ __align__(128) unsigned char g_wsw[8][64][16*4096];
__device__ __align__(16) float g_s[8][BB*NH];     // fp32 states s0..s7
__device__ __align__(16) float g_hbuf[BB*NH];
__device__ unsigned g_arrive, g_epoch;

// ---------------- primitives ----------------
__device__ __forceinline__ void mma16816(float c[4], const uint32_t a[4],
                                         uint32_t b0, uint32_t b1){
  asm volatile(
    "mma.sync.aligned.m16n8k16.row.col.f32.f16.f16.f32 "
    "{%0,%1,%2,%3},{%4,%5,%6,%7},{%8,%9},{%0,%1,%2,%3};\n"
    : "+f"(c[0]), "+f"(c[1]), "+f"(c[2]), "+f"(c[3])
    : "r"(a[0]), "r"(a[1]), "r"(a[2]), "r"(a[3]), "r"(b0), "r"(b1));
}

__device__ __forceinline__ void ldsm4(uint32_t r[4], uint32_t addr){
  asm volatile("ldmatrix.sync.aligned.m8n8.x4.shared.b16 {%0,%1,%2,%3}, [%4];"
    : "=r"(r[0]), "=r"(r[1]), "=r"(r[2]), "=r"(r[3]) : "r"(addr));
}

__device__ __forceinline__ void bulkcp(uint32_t dst, const void* src, uint32_t bytes, uint32_t mbar){
  asm volatile(
    "cp.async.bulk.shared::cta.global.mbarrier::complete_tx::bytes [%0], [%1], %2, [%3];"
    :: "r"(dst), "l"(src), "r"(bytes), "r"(mbar) : "memory");
}

__device__ __forceinline__ void expect_tx(uint32_t mbar, uint32_t bytes){
  asm volatile("mbarrier.arrive.expect_tx.shared.b64 _, [%0], %1;"
    :: "r"(mbar), "r"(bytes) : "memory");
}

__device__ __forceinline__ void mbar_wait(uint32_t mbar, int phase){
  uint32_t done;
  asm volatile(
    "{\n\t.reg .pred p;\n\t"
    "mbarrier.try_wait.parity.acquire.cta.shared::cta.b64 p, [%1], %2;\n\t"
    "selp.b32 %0, 1, 0, p;\n\t}"
    : "=r"(done) : "r"(mbar), "r"((uint32_t)phase) : "memory");
  if (!done){
    asm volatile(
      "{\n\t.reg .pred P1;\n\t"
      "WAIT_LOOP_%=:\n\t"
      "mbarrier.try_wait.parity.acquire.cta.shared::cta.b64 P1, [%0], %1, 0x989680;\n\t"
      "@P1 bra.uni WAIT_DONE_%=;\n\t"
      "bra.uni WAIT_LOOP_%=;\n\t"
      "WAIT_DONE_%=:\n\t}"
      :: "r"(mbar), "r"((uint32_t)phase) : "memory");
  }
}

__device__ __forceinline__ void gsync(unsigned &target){
  __syncthreads();
  if (threadIdx.x == 0){
    target += gridDim.x;
    unsigned old;
    asm volatile("atom.add.release.gpu.global.u32 %0, [%1], %2;"
                 : "=r"(old) : "l"(&g_arrive), "r"(1u) : "memory");
    if (old + 1 == target){
      asm volatile("st.release.gpu.global.u32 [%0], %1;" :: "l"(&g_epoch), "r"(target) : "memory");
    } else {
      unsigned e; int spins = 0;
      do {
        asm volatile("ld.acquire.gpu.global.u32 %0, [%1];" : "=r"(e) : "l"(&g_epoch) : "memory");
        if (++spins > 32) __nanosleep(64);
      } while ((int)(e - target) < 0);
    }
  }
  __syncthreads();
}

__device__ __forceinline__ float act_fn(int act, float v){
  switch (act){
    case 0:  return 1.f/(1.f + __expf(-v));
    case 1:  return fmaxf(v, 0.f);
    case 2:  return v;
    default: return tanhf(v);
  }
}

// write fp16 value into swizzled state layout: base points at [2][16][8192] block
__device__ __forceinline__ void st_swz(unsigned char* base, int m, int k, __half v){
  unsigned char* p = base + ((size_t)((m>>6)*16 + (k>>6)))*8192;
  uint32_t o = (uint32_t)((m&63)*128 + (k&63)*2);
  o ^= (o>>3)&0x70;
  *(__half*)(p + o) = v;
}

// ---------------- GEMM job ----------------
// M=64 rows [m0,m0+64), 16 output cols (pairs) [j0t*16, +16).
// A source: swizzled 16-subtile half-blocks a1 (k<1024) / a2 (k>=1024, G0 only).
// W source: pre-interleaved swizzled job block(s) w1 (+w2 if FUSED).
// FUSED: genes 5+7 together; epilogue computes s6,s8, h=mean(s1..s8), writes out.
template<bool FUSED>
__device__ void job(
    const unsigned char* a1, const unsigned char* a2,
    const unsigned char* w1, const unsigned char* w2,
    const float* __restrict__ resid, float* __restrict__ outS, unsigned char* swz,
    int m0, int j0t, int act, int NC,
    uint32_t sbase, uint32_t mb0, int ph[3], int tid,
    float* __restrict__ out, int t)
{
  const int lane = tid & 31, warp = tid >> 5;
  const int wm = warp >> 1, wn = warp & 1;
  const uint32_t TX = FUSED ? 65536u : 49152u;

  float C[FUSED?4:2][4];
  #pragma unroll
  for (int n=0;n<(FUSED?4:2);n++)
    #pragma unroll
    for (int q=0;q<4;q++) C[n][q]=0.f;

  auto load_chunk = [&](int c, int st){
    if (tid == 0){
      uint32_t mbar = mb0 + st*8;
      int k0 = c*256;
      uint32_t d = sbase + st*STAGE;
      const unsigned char* as = (a2 && k0 >= 1024)
          ? (a2 + ((size_t)((k0-1024)>>6))*8192)
          : (a1 + ((size_t)(k0>>6))*8192);
      bulkcp(d, as, 32768u, mbar);
      bulkcp(d + 32768u, w1 + ((size_t)(k0>>6))*4096, 16384u, mbar);
      if (FUSED) bulkcp(d + 49152u, w2 + ((size_t)(k0>>6))*4096, 16384u, mbar);
    }
  };

  if (tid == 0){
    expect_tx(mb0,    TX);
    expect_tx(mb0+8,  TX);
    expect_tx(mb0+16, TX);
  }
  __syncthreads();
  load_chunk(0,0); load_chunk(1,1); load_chunk(2,2);

  // per-lane LDSM address components (swizzle XOR is row-dependent constant)
  const uint32_t a_row = (uint32_t)(wm*16 + (lane & 15));
  const uint32_t a_kb  = (uint32_t)((lane >> 4) * 16);
  const int sub2 = lane >> 3;
  const uint32_t b_row = (uint32_t)(wn*16 + ((sub2 >> 1) << 3) + (lane & 7));
  const uint32_t b_kb  = (uint32_t)((sub2 & 1) * 16);
  const uint32_t aXor = (a_row & 7) << 4;
  const uint32_t bXor = (b_row & 7) << 4;
  const uint32_t aOff = a_row * 128;
  const uint32_t bOff = b_row * 128;

  for (int c=0; c<NC; c++){
    const int st = c % 3;
    const uint32_t mbar = mb0 + st*8;
    mbar_wait(mbar, ph[st]); ph[st] ^= 1;
    if (c + 3 < NC && tid == 0) expect_tx(mbar, TX);

    const uint32_t base = sbase + st*STAGE;
    #pragma unroll
    for (int sub=0; sub<4; sub++){
      const uint32_t aSub = base + sub*8192 + aOff;
      const uint32_t wSub = base + 32768 + sub*4096 + bOff;
      #pragma unroll
      for (int k16=0; k16<4; k16++){
        const uint32_t ak = (((uint32_t)(k16*32) + a_kb) ^ aXor);
        const uint32_t bk = (((uint32_t)(k16*32) + b_kb) ^ bXor);
        uint32_t A4[4], B4[4];
        ldsm4(A4, aSub + ak);
        ldsm4(B4, wSub + bk);
        mma16816(C[0], A4, B4[0], B4[1]);
        mma16816(C[1], A4, B4[2], B4[3]);
        if (FUSED){
          uint32_t B7[4];
          ldsm4(B7, wSub + 16384 + bk);
          mma16816(C[2], A4, B7[0], B7[1]);
          mma16816(C[3], A4, B7[2], B7[3]);
        }
      }
    }
    __syncthreads();
    if (c + 3 < NC) load_chunk(c+3, st);
  }

  // epilogue: C[f][0]=c@m, C[f][1]=h@m, C[f][2]=c@m+8, C[f][3]=h@m+8
  #pragma unroll
  for (int f=0; f<2; f++){
    const int col = j0t*16 + wn*8 + f*4 + (lane & 3);
    #pragma unroll
    for (int hf=0; hf<2; hf++){
      const int m = m0 + wm*16 + (lane>>2) + hf*8;
      const int idx = m*NH + col;
      if (!FUSED){
        float cv = C[f][hf*2], hv = C[f][hf*2+1];
        float sp = __ldcg(resid + idx);
        float g = 1.f/(1.f + __expf(-cv));
        float v = fmaf(g, act_fn(act, hv) - sp, sp);
        outS[idx] = v;
        if (swz) st_swz(swz, m, col, __float2half_rn(v));
      } else {
        float s5v = __ldcg(resid + idx);
        float g5 = 1.f/(1.f + __expf(-C[f][hf*2]));
        float s6 = fmaf(g5, 1.f/(1.f + __expf(-C[f][hf*2+1])) - s5v, s5v);
        float g7 = 1.f/(1.f + __expf(-C[2+f][hf*2]));
        float s8 = fmaf(g7, fmaxf(C[2+f][hf*2+1], 0.f) - s5v, s5v);
        float mv = (__ldcg(&g_s[1][idx]) + __ldcg(&g_s[2][idx]) +
                    __ldcg(&g_s[3][idx]) + __ldcg(&g_s[4][idx]) +
                    s5v + s6 + __ldcg(&g_s[7][idx]) + s8) * 0.125f;
        g_hbuf[idx] = mv;
        st_swz(&g_sw[6][0][0][0], m, col, __float2half_rn(mv));
        out[((size_t)m*TT + t)*NH + col] = mv;
        if (t == TT-1) out[(size_t)BB*TT*NH + idx] = mv;
      }
    }
  }
}

// ---------------- persistent scan kernel ----------------
__global__ void __launch_bounds__(NT,1) rnn_persistent(float* __restrict__ out){
  extern __shared__ __align__(128) unsigned char dsm[];
  __shared__ __align__(8) uint64_t s_mbar[3];

  const int tid = threadIdx.x;
  uint32_t sbase, mb0;
  { uint32_t a; asm("{ .reg .u64 t; cvta.to.shared.u64 t, %1; cvt.u32.u64 %0, t; }" : "=r"(a) : "l"(dsm)); sbase = a; }
  { uint32_t a; asm("{ .reg .u64 t; cvta.to.shared.u64 t, %1; cvt.u32.u64 %0, t; }" : "=r"(a) : "l"(&s_mbar[0])); mb0 = a; }

  if (tid == 0){
    #pragma unroll
    for (int b=0;b<3;b++)
      asm volatile("mbarrier.init.shared.b64 [%0], %1;" :: "r"(mb0+b*8), "r"(1u) : "memory");
  }
  __syncthreads();

  int ph[3] = {0,0,0};
  unsigned target = 0;

  for (int t = 0; t < TT; t++){
    // G0: [x_t | h] @ W0 -> s0 (tanh, resid h). 128 jobs, K=2048
    for (int it = blockIdx.x; it < 128; it += gridDim.x){
      int half = (it >= 64), j0t = it & 63;
      job<false>(&g_xw[t][half][0][0], &g_sw[6][half][0][0], g_w0w[j0t], nullptr,
                 g_hbuf, g_s[0], &g_sw[0][0][0][0],
                 half*64, j0t, 3, 8, sbase, mb0, ph, tid, out, t);
    }
    gsync(target);

    // G1: gene0 (sigmoid) s0 -> s1. 128 jobs
    for (int it = blockIdx.x; it < 128; it += gridDim.x){
      int half = (it >= 64), j0t = it & 63;
      job<false>(&g_sw[0][half][0][0], nullptr, g_wsw[0][j0t], nullptr,
                 g_s[0], g_s[1], &g_sw[1][0][0][0],
                 half*64, j0t, 0, 4, sbase, mb0, ph, tid, out, t);
    }
    gsync(target);

    // G2: genes 1,2,3 from s1 -> s2(relu), s3(relu), s4(identity). 384 jobs
    for (int it = blockIdx.x; it < 384; it += gridDim.x){
      int gi = 1 + (it >> 7), rem = it & 127;
      int half = (rem >= 64), j0t = rem & 63;
      int dst = gi + 1;
      job<false>(&g_sw[1][half][0][0], nullptr, g_wsw[gi][j0t], nullptr,
                 g_s[1], g_s[dst], (dst < 4) ? &g_sw[dst][0][0][0] : (unsigned char*)nullptr,
                 half*64, j0t, (gi==3)?2:1, 4, sbase, mb0, ph, tid, out, t);
    }
    gsync(target);

    // G3: gene4 (tanh) s2->s5 ; gene6 (tanh) s3->s7. 256 jobs
    for (int it = blockIdx.x; it < 256; it += gridDim.x){
      int slot = it >> 7, rem = it & 127;
      int half = (rem >= 64), j0t = rem & 63;
      int gi = 4 + slot*2, src = 2 + slot, dst = gi + 1;  // 5 or 7
      job<false>(&g_sw[src][half][0][0], nullptr, g_wsw[gi][j0t], nullptr,
                 g_s[src], g_s[dst], (dst==5) ? &g_sw[5][0][0][0] : (unsigned char*)nullptr,
                 half*64, j0t, 3, 4, sbase, mb0, ph, tid, out, t);
    }
    gsync(target);

    // G4+F fused: genes 5+7 from s5 -> s6,s8 local; h=mean(s1..s8); out writes
    for (int it = blockIdx.x; it < 128; it += gridDim.x){
      int half = (it >= 64), j0t = it & 63;
      job<true>(&g_sw[5][half][0][0], nullptr, g_wsw[5][j0t], g_wsw[7][j0t],
                g_s[5], nullptr, nullptr,
                half*64, j0t, 0, 4, sbase, mb0, ph, tid, out, t);
    }
    gsync(target);
  }
}

// ---------------- prologue kernels ----------------
// weights: fp32 [K][2048] -> interleaved+swizzled job blocks
__global__ void wswz(const float* __restrict__ in, unsigned char* __restrict__ outp, int K){
  __shared__ float tile[32][65];   // [w][k]
  const float* src = in + (size_t)blockIdx.z*K*2048;
  unsigned char* dst = outp + (((size_t)blockIdx.z*64 + blockIdx.x)*(K/64) + blockIdx.y)*4096;
  int j0 = blockIdx.x*16, k0 = blockIdx.y*64;
  int tx = threadIdx.x, ty = threadIdx.y;     // 32 x 8
  int w = tx;
  int col = (j0 + (w>>1)) + (w&1)*1024;       // interleave: row 2p=c, 2p+1=h
  for (int r=0;r<8;r++){
    int k = ty + r*8;
    tile[w][k] = src[(size_t)(k0+k)*2048 + col];
  }
  __syncthreads();
  for (int q=0;q<4;q++){
    int ww = ty + q*8;
    __half2 v = __floats2half2_rn(tile[ww][tx*2], tile[ww][tx*2+1]);
    uint32_t o = (uint32_t)(ww*128 + tx*4);
    o ^= (o>>3)&0x70;
    *(__half2*)(dst + o) = v;
  }
}

// x: [B][T][NI] fp32 -> swizzled [t][half][subtile][8192]
__global__ void xswz(const float* __restrict__ x, unsigned char* __restrict__ xs){
  int t = blockIdx.x;
  int half = blockIdx.y >> 4, st = blockIdx.y & 15;
  unsigned char* dst = xs + (((size_t)t*2 + half)*16 + st)*8192;
  int tid = threadIdx.x;
  int row = tid >> 2, kq = (tid & 3)*16;
  const float* src = x + ((size_t)(half*64 + row)*TT + t)*NI + st*64 + kq;
  #pragma unroll
  for (int i=0;i<2;i++){
    float4 a = *(const float4*)(src + i*8);
    float4 b = *(const float4*)(src + i*8 + 4);
    __half2 h0 = __floats2half2_rn(a.x,a.y), h1 = __floats2half2_rn(a.z,a.w);
    __half2 h2 = __floats2half2_rn(b.x,b.y), h3 = __floats2half2_rn(b.z,b.w);
    uint32_t o = (uint32_t)(row*128 + (kq + i*8)*2);
    o ^= (o>>3)&0x70;
    *(uint4*)(dst + o) = make_uint4(*(uint32_t*)&h0, *(uint32_t*)&h1,
                                    *(uint32_t*)&h2, *(uint32_t*)&h3);
  }
}

// h0 -> g_hbuf fp32 + swizzled state 6
__global__ void hswz(const float* __restrict__ h0){
  int tid = blockIdx.x*blockDim.x + threadIdx.x;   // 131072 elems
  int m = tid >> 10, k = tid & 1023;
  float v = h0[tid];
  g_hbuf[tid] = v;
  st_swz(&g_sw[6][0][0][0], m, k, __float2half_rn(v));
}

__global__ void reset_kernel(){ g_arrive = 0; g_epoch = 0; }

// ---------------- host launch ----------------
extern "C" void kernel_launch(void* const* d_in, const int* in_sizes, int n_in,
                              void* d_out, int out_size){
  const float *x=nullptr, *h0=nullptr, *W0=nullptr, *Ws=nullptr;
  for (int i=0;i<n_in;i++){
    long n = in_sizes[i];
    if      (n == (long)BB*TT*NI)   x  = (const float*)d_in[i];
    else if (n == (long)BB*NH)      h0 = (const float*)d_in[i];
    else if (n == (long)2048*2048)  W0 = (const float*)d_in[i];
    else if (n == (long)8*NH*2048)  Ws = (const float*)d_in[i];
  }
  if (!x || !h0 || !W0 || !Ws) return;
  float* out = (float*)d_out;

  void* p;
  cudaGetSymbolAddress(&p, g_xw);  unsigned char* xw_p = (unsigned char*)p;
  cudaGetSymbolAddress(&p, g_w0w); unsigned char* w0_p = (unsigned char*)p;
  cudaGetSymbolAddress(&p, g_wsw); unsigned char* ws_p = (unsigned char*)p;

  cudaFuncSetAttribute(rnn_persistent, cudaFuncAttributeMaxDynamicSharedMemorySize, SMEM_DYN);

  int dev = 0, nsm = 0;
  cudaGetDevice(&dev);
  cudaDeviceGetAttribute(&nsm, cudaDevAttrMultiProcessorCount, dev);

  // prologue: swizzle weights / inputs / initial hidden
  wswz<<<dim3(64,32,1), dim3(32,8)>>>(W0, w0_p, 2048);
  wswz<<<dim3(64,16,8), dim3(32,8)>>>(Ws, ws_p, 1024);
  xswz<<<dim3(TT,32), 256>>>(x, xw_p);
  hswz<<<512,256>>>(h0);
  reset_kernel<<<1,1>>>();

  rnn_persistent<<<nsm, NT, SMEM_DYN>>>(out);
  (void)out_size;
}